// round 1
// baseline (speedup 1.0000x reference)
#include <cuda_runtime.h>
#include <math.h>

// ---------------- problem constants ----------------
#define NE     100000        // entities
#define NU     50000         // users
#define NEDGE  2000000
#define NNZV   1000000
#define CH     128
#define C4     32            // CH/4
#define RR0    42033
#define RR1    44630
#define RM     (RR1-RR0)     // 2597
#define NREL   25
#define NHOPS  3

// ---------------- device scratch (no allocations allowed) ----------------
__device__ float g_E0[NE*CH];
__device__ float g_E1[NE*CH];
__device__ float g_region[RM*CH];
__device__ int   g_cnt_e[NE];
__device__ int   g_rowptr_e[NE+1];
__device__ int   g_cursor_e[NE];
__device__ int   g_pack[NEDGE];          // tail | ((type-1)<<17)
__device__ int   g_cnt_u[NU];
__device__ int   g_rowptr_u[NU+1];
__device__ int   g_cursor_u[NU];
__device__ int   g_ucol[NNZV];
__device__ float g_uval[NNZV];
__device__ int   g_bsums[256];

// ---------------- small helpers ----------------
__global__ void k_count(const int* __restrict__ idx, int n, int* __restrict__ cnt) {
    int i = blockIdx.x * blockDim.x + threadIdx.x;
    if (i < n) atomicAdd(&cnt[idx[i]], 1);
}

// block-wise exclusive scan (1024/block), writes per-block totals
__global__ void k_scan_block(const int* __restrict__ in, int* __restrict__ out,
                             int* __restrict__ bsums, int n) {
    __shared__ int s[1024];
    int i = blockIdx.x * 1024 + threadIdx.x;
    int v = (i < n) ? in[i] : 0;
    s[threadIdx.x] = v;
    __syncthreads();
    for (int off = 1; off < 1024; off <<= 1) {
        int t = (threadIdx.x >= off) ? s[threadIdx.x - off] : 0;
        __syncthreads();
        s[threadIdx.x] += t;
        __syncthreads();
    }
    if (i < n) out[i] = s[threadIdx.x] - v;   // exclusive
    if (threadIdx.x == 1023) bsums[blockIdx.x] = s[1023];
}

// single-block exclusive scan of block sums (nb <= 128)
__global__ void k_scan_sums(int* __restrict__ bsums, int nb) {
    __shared__ int s[128];
    int v = (threadIdx.x < nb) ? bsums[threadIdx.x] : 0;
    s[threadIdx.x] = v;
    __syncthreads();
    for (int off = 1; off < 128; off <<= 1) {
        int t = (threadIdx.x >= off) ? s[threadIdx.x - off] : 0;
        __syncthreads();
        s[threadIdx.x] += t;
        __syncthreads();
    }
    if (threadIdx.x < nb) bsums[threadIdx.x] = s[threadIdx.x] - v;  // exclusive
}

__global__ void k_scan_add(int* __restrict__ rowptr, const int* __restrict__ bsums,
                           int* __restrict__ cursor, int n, int total) {
    int i = blockIdx.x * 1024 + threadIdx.x;
    if (i < n) {
        int v = rowptr[i] + bsums[blockIdx.x];
        rowptr[i] = v;
        cursor[i] = v;
    }
    if (i == 0) rowptr[n] = total;
}

__global__ void k_fill_edges(const int* __restrict__ head, const int* __restrict__ tail,
                             const int* __restrict__ type, int n) {
    int i = blockIdx.x * blockDim.x + threadIdx.x;
    if (i < n) {
        int pos = atomicAdd(&g_cursor_e[head[i]], 1);
        g_pack[pos] = tail[i] | ((type[i] - 1) << 17);
    }
}

__global__ void k_fill_users(const int* __restrict__ rows, const int* __restrict__ cols,
                             const float* __restrict__ vals, int n) {
    int i = blockIdx.x * blockDim.x + threadIdx.x;
    if (i < n) {
        int pos = atomicAdd(&g_cursor_u[rows[i]], 1);
        g_ucol[pos] = cols[i];
        g_uval[pos] = vals[i];
    }
}

// ---------------- region GEMM:  C[RM x 128] = A[RM x RM] * B[RM x 128] ----------------
// BM=16, BK=64, 256 threads; warp = one ty -> As reads are warp-broadcast.
__global__ __launch_bounds__(256)
void k_gemm_region(const float* __restrict__ A, const float* __restrict__ B,
                   float* __restrict__ Cout) {
    const int BM = 16, BK = 64;
    __shared__ float As[BM * BK];
    __shared__ float Bs[BK * CH];
    int bm = blockIdx.x * BM;
    int tx = threadIdx.x & 31;        // col group (4 cols each)
    int ty = threadIdx.x >> 5;        // 0..7
    int r0 = ty * 2, r1 = ty * 2 + 1; // local rows

    float acc00 = 0, acc01 = 0, acc02 = 0, acc03 = 0;
    float acc10 = 0, acc11 = 0, acc12 = 0, acc13 = 0;

    for (int k0 = 0; k0 < RM; k0 += BK) {
        // load A tile (scalar, coalesced by col)
        for (int e = threadIdx.x; e < BM * BK; e += 256) {
            int r = e >> 6, c = e & 63;
            int gr = bm + r, gc = k0 + c;
            As[e] = (gr < RM && gc < RM) ? A[gr * RM + gc] : 0.f;
        }
        // load B tile (float4)
        for (int e = threadIdx.x; e < BK * C4; e += 256) {
            int r = e >> 5, c4 = e & 31;
            int gk = k0 + r;
            float4 v = (gk < RM) ? reinterpret_cast<const float4*>(B)[gk * C4 + c4]
                                 : make_float4(0.f, 0.f, 0.f, 0.f);
            reinterpret_cast<float4*>(Bs)[e] = v;
        }
        __syncthreads();
        #pragma unroll
        for (int k = 0; k < BK; k++) {
            float a0 = As[r0 * BK + k];
            float a1 = As[r1 * BK + k];
            float4 b = reinterpret_cast<float4*>(Bs)[k * C4 + tx];
            acc00 += a0 * b.x; acc01 += a0 * b.y; acc02 += a0 * b.z; acc03 += a0 * b.w;
            acc10 += a1 * b.x; acc11 += a1 * b.y; acc12 += a1 * b.z; acc13 += a1 * b.w;
        }
        __syncthreads();
    }
    int gr0 = bm + r0, gr1 = bm + r1;
    if (gr0 < RM)
        reinterpret_cast<float4*>(Cout)[gr0 * C4 + tx] = make_float4(acc00, acc01, acc02, acc03);
    if (gr1 < RM)
        reinterpret_cast<float4*>(Cout)[gr1 * C4 + tx] = make_float4(acc10, acc11, acc12, acc13);
}

__global__ void k_blend(float* __restrict__ E) {
    int i = blockIdx.x * blockDim.x + threadIdx.x;
    if (i < RM * CH) {
        float* p = &E[RR0 * CH + i];
        *p = 0.8f * (*p) + 0.2f * g_region[i];
    }
}

// ---------------- KG aggregate: warp per entity, fused mean + l2norm + residual --------
__global__ __launch_bounds__(256)
void k_entity_agg(const float4* __restrict__ E, float4* __restrict__ Enext,
                  float* __restrict__ res, const float* __restrict__ W) {
    __shared__ float4 sW[NREL * C4];   // 12.8 KB relation weights
    for (int e = threadIdx.x; e < NREL * C4; e += blockDim.x)
        sW[e] = reinterpret_cast<const float4*>(W)[e];
    __syncthreads();

    int warp = (blockIdx.x * blockDim.x + threadIdx.x) >> 5;
    int lane = threadIdx.x & 31;
    if (warp >= NE) return;

    int start = g_rowptr_e[warp];
    int end   = g_rowptr_e[warp + 1];

    float4 acc = make_float4(0.f, 0.f, 0.f, 0.f);
    for (int base = start; base < end; base += 32) {
        int p = (base + lane < end) ? g_pack[base + lane] : 0;
        int m = min(32, end - base);
        for (int j = 0; j < m; j++) {
            int pj = __shfl_sync(0xffffffffu, p, j);
            int tail = pj & 0x1FFFF;
            int t    = pj >> 17;
            float4 ev = E[tail * C4 + lane];
            float4 w  = sW[t * C4 + lane];
            acc.x += ev.x * w.x; acc.y += ev.y * w.y;
            acc.z += ev.z * w.z; acc.w += ev.w * w.w;
        }
    }
    int cnt = end - start;
    float inv = cnt ? (1.f / (float)cnt) : 0.f;
    acc.x *= inv; acc.y *= inv; acc.z *= inv; acc.w *= inv;

    float ss = acc.x * acc.x + acc.y * acc.y + acc.z * acc.z + acc.w * acc.w;
    #pragma unroll
    for (int o = 16; o; o >>= 1) ss += __shfl_xor_sync(0xffffffffu, ss, o);
    float scale = 1.f / fmaxf(sqrtf(ss), 1e-12f);
    float4 o4 = make_float4(acc.x * scale, acc.y * scale, acc.z * scale, acc.w * scale);

    Enext[warp * C4 + lane] = o4;
    float4* r4 = reinterpret_cast<float4*>(res);
    float4 rv = r4[warp * C4 + lane];
    rv.x += o4.x; rv.y += o4.y; rv.z += o4.z; rv.w += o4.w;
    r4[warp * C4 + lane] = rv;
}

// ---------------- user aggregate: warp per user, fused l2norm + residual ---------------
__global__ __launch_bounds__(256)
void k_user_agg(const float4* __restrict__ E, float* __restrict__ resU) {
    int warp = (blockIdx.x * blockDim.x + threadIdx.x) >> 5;
    int lane = threadIdx.x & 31;
    if (warp >= NU) return;

    int start = g_rowptr_u[warp];
    int end   = g_rowptr_u[warp + 1];

    float4 acc = make_float4(0.f, 0.f, 0.f, 0.f);
    for (int base = start; base < end; base += 32) {
        int c = (base + lane < end) ? g_ucol[base + lane] : 0;
        float v = (base + lane < end) ? g_uval[base + lane] : 0.f;
        int m = min(32, end - base);
        for (int j = 0; j < m; j++) {
            int   cj = __shfl_sync(0xffffffffu, c, j);
            float vj = __shfl_sync(0xffffffffu, v, j);
            float4 ev = E[cj * C4 + lane];
            acc.x += vj * ev.x; acc.y += vj * ev.y;
            acc.z += vj * ev.z; acc.w += vj * ev.w;
        }
    }
    float ss = acc.x * acc.x + acc.y * acc.y + acc.z * acc.z + acc.w * acc.w;
    #pragma unroll
    for (int o = 16; o; o >>= 1) ss += __shfl_xor_sync(0xffffffffu, ss, o);
    float scale = 1.f / fmaxf(sqrtf(ss), 1e-12f);
    float4 o4 = make_float4(acc.x * scale, acc.y * scale, acc.z * scale, acc.w * scale);

    float4* r4 = reinterpret_cast<float4*>(resU);
    float4 rv = r4[warp * C4 + lane];
    rv.x += o4.x; rv.y += o4.y; rv.z += o4.z; rv.w += o4.w;
    r4[warp * C4 + lane] = rv;
}

// ---------------- launch ----------------
extern "C" void kernel_launch(void* const* d_in, const int* in_sizes, int n_in,
                              void* d_out, int out_size) {
    const float* user_emb   = (const float*)d_in[0];
    const float* entity_emb = (const float*)d_in[1];
    const float* rwm        = (const float*)d_in[2];
    const float* weight     = (const float*)d_in[3];
    const float* ivals      = (const float*)d_in[4];
    const int*   ehead      = (const int*)d_in[5];
    const int*   etail      = (const int*)d_in[6];
    const int*   etype      = (const int*)d_in[7];
    const int*   irows      = (const int*)d_in[8];
    const int*   icols      = (const int*)d_in[9];
    float* out = (float*)d_out;

    float *pE0, *pE1, *pRegion;
    int *pCntE, *pRowE, *pCurE, *pCntU, *pRowU, *pCurU, *pBs;
    cudaGetSymbolAddress((void**)&pE0, g_E0);
    cudaGetSymbolAddress((void**)&pE1, g_E1);
    cudaGetSymbolAddress((void**)&pRegion, g_region);
    cudaGetSymbolAddress((void**)&pCntE, g_cnt_e);
    cudaGetSymbolAddress((void**)&pRowE, g_rowptr_e);
    cudaGetSymbolAddress((void**)&pCurE, g_cursor_e);
    cudaGetSymbolAddress((void**)&pCntU, g_cnt_u);
    cudaGetSymbolAddress((void**)&pRowU, g_rowptr_u);
    cudaGetSymbolAddress((void**)&pCurU, g_cursor_u);
    cudaGetSymbolAddress((void**)&pBs, g_bsums);

    // -- residual init + working entity buffer init
    cudaMemcpyAsync(out, entity_emb, (size_t)NE * CH * sizeof(float), cudaMemcpyDeviceToDevice);
    cudaMemcpyAsync(out + (size_t)NE * CH, user_emb, (size_t)NU * CH * sizeof(float),
                    cudaMemcpyDeviceToDevice);
    cudaMemcpyAsync(pE0, entity_emb, (size_t)NE * CH * sizeof(float), cudaMemcpyDeviceToDevice);

    // -- CSR build (once; reused across hops)
    cudaMemsetAsync(pCntE, 0, NE * sizeof(int));
    cudaMemsetAsync(pCntU, 0, NU * sizeof(int));
    k_count<<<(NEDGE + 255) / 256, 256>>>(ehead, NEDGE, pCntE);
    k_count<<<(NNZV + 255) / 256, 256>>>(irows, NNZV, pCntU);

    int nbE = (NE + 1023) / 1024;   // 98
    int nbU = (NU + 1023) / 1024;   // 49
    k_scan_block<<<nbE, 1024>>>(pCntE, pRowE, pBs, NE);
    k_scan_sums<<<1, 128>>>(pBs, nbE);
    k_scan_add<<<nbE, 1024>>>(pRowE, pBs, pCurE, NE, NEDGE);
    k_scan_block<<<nbU, 1024>>>(pCntU, pRowU, pBs, NU);
    k_scan_sums<<<1, 128>>>(pBs, nbU);
    k_scan_add<<<nbU, 1024>>>(pRowU, pBs, pCurU, NU, NNZV);

    k_fill_edges<<<(NEDGE + 255) / 256, 256>>>(ehead, etail, etype, NEDGE);
    k_fill_users<<<(NNZV + 255) / 256, 256>>>(irows, icols, ivals, NNZV);

    // -- hops
    float* Ecur = pE0;
    float* Enxt = pE1;
    for (int h = 0; h < NHOPS; h++) {
        k_gemm_region<<<(RM + 15) / 16, 256>>>(rwm, Ecur + (size_t)RR0 * CH, pRegion);
        k_blend<<<(RM * CH + 255) / 256, 256>>>(Ecur);
        k_entity_agg<<<(NE + 7) / 8, 256>>>((const float4*)Ecur, (float4*)Enxt, out, weight);
        k_user_agg<<<(NU + 7) / 8, 256>>>((const float4*)Ecur, out + (size_t)NE * CH);
        float* t = Ecur; Ecur = Enxt; Enxt = t;
    }
}

// round 2
// speedup vs baseline: 1.4394x; 1.4394x over previous
#include <cuda_runtime.h>
#include <math.h>

// ---------------- problem constants ----------------
#define NE     100000
#define NU     50000
#define NTOT   (NE+NU)
#define NEDGE  2000000
#define NNZV   1000000
#define CH     128
#define C4     32
#define RR0    42033
#define RR1    44630
#define RM     (RR1-RR0)     // 2597
#define NREL   25
#define NHOPS  3
#define SK     4             // split-K for region gemm
#define KSLICE 650           // ceil(RM/SK)
#define NSCAN  147           // ceil(NTOT/1024)

// ---------------- device scratch ----------------
__device__ float g_E0[NE*CH];
__device__ float g_E1[NE*CH];
__device__ float g_regp[SK*RM*CH];     // split-K partials
__device__ int   g_cnt[NTOT];
__device__ int   g_rowptr[NTOT+1];
__device__ int   g_cursor[NTOT];
__device__ int   g_pack[NEDGE];        // tail | ((type-1)<<17)
__device__ int   g_ucol[NNZV];
__device__ float g_uval[NNZV];
__device__ unsigned long long g_lb[NSCAN];  // lookback: state<<32 | value

// ---------------- CSR build ----------------
__global__ void k_count(const int* __restrict__ ehead, const int* __restrict__ irows) {
    int i = blockIdx.x * blockDim.x + threadIdx.x;
    if (i < NEDGE) atomicAdd(&g_cnt[ehead[i]], 1);
    else if (i < NEDGE + NNZV) atomicAdd(&g_cnt[NE + irows[i - NEDGE]], 1);
}

// one-kernel decoupled-lookback exclusive scan over g_cnt -> g_rowptr/g_cursor
__global__ __launch_bounds__(1024)
void k_scan_lb() {
    __shared__ int s[1024];
    __shared__ int s_prefix;
    int b = blockIdx.x, t = threadIdx.x;
    int i = b * 1024 + t;
    int v = (i < NTOT) ? g_cnt[i] : 0;
    s[t] = v;
    __syncthreads();
    #pragma unroll
    for (int off = 1; off < 1024; off <<= 1) {
        int tmp = (t >= off) ? s[t - off] : 0;
        __syncthreads();
        s[t] += tmp;
        __syncthreads();
    }
    int incl = s[t];
    int total = s[1023];
    if (t == 0) {
        if (b == 0) {
            atomicExch(&g_lb[0], (2ULL << 32) | (unsigned)total);
            s_prefix = 0;
        } else {
            atomicExch(&g_lb[b], (1ULL << 32) | (unsigned)total);
            long long ex = 0;
            int idx = b - 1;
            while (true) {
                unsigned long long pk;
                do { pk = atomicAdd(&g_lb[idx], 0ULL); } while ((pk >> 32) == 0);
                ex += (unsigned)pk;
                if ((pk >> 32) == 2ULL) break;
                idx--;
            }
            atomicExch(&g_lb[b], (2ULL << 32) | (unsigned)(ex + total));
            s_prefix = (int)ex;
        }
    }
    __syncthreads();
    int excl = s_prefix + incl - v;
    if (i < NTOT) { g_rowptr[i] = excl; g_cursor[i] = excl; }
    if (i == NTOT - 1) g_rowptr[NTOT] = NEDGE + NNZV;
}

__global__ void k_fill(const int* __restrict__ ehead, const int* __restrict__ etail,
                       const int* __restrict__ etype, const int* __restrict__ irows,
                       const int* __restrict__ icols, const float* __restrict__ ivals) {
    int i = blockIdx.x * blockDim.x + threadIdx.x;
    if (i < NEDGE) {
        int pos = atomicAdd(&g_cursor[ehead[i]], 1);
        g_pack[pos] = etail[i] | ((etype[i] - 1) << 17);
    } else if (i < NEDGE + NNZV) {
        int k = i - NEDGE;
        int pos = atomicAdd(&g_cursor[NE + irows[k]], 1) - NEDGE;
        g_ucol[pos] = icols[k];
        g_uval[pos] = ivals[k];
    }
}

// ---------------- region GEMM, split-K ----------------
// grid = (163, SK); block 256; BM=16. Partial sums -> g_regp[sk].
__global__ __launch_bounds__(256)
void k_gemm_region(const float* __restrict__ A, const float* __restrict__ B) {
    const int BM = 16, BK = 64;
    __shared__ float As[BM * BK];
    __shared__ float Bs[BK * CH];
    int bm = blockIdx.x * BM;
    int sk = blockIdx.y;
    int kb = sk * KSLICE;
    int ke = min(kb + KSLICE, RM);
    int tx = threadIdx.x & 31;
    int ty = threadIdx.x >> 5;
    int r0 = ty * 2, r1 = ty * 2 + 1;

    float acc00 = 0, acc01 = 0, acc02 = 0, acc03 = 0;
    float acc10 = 0, acc11 = 0, acc12 = 0, acc13 = 0;

    for (int k0 = kb; k0 < ke; k0 += BK) {
        for (int e = threadIdx.x; e < BM * BK; e += 256) {
            int r = e >> 6, c = e & 63;
            int gr = bm + r, gc = k0 + c;
            As[e] = (gr < RM && gc < ke) ? A[gr * RM + gc] : 0.f;
        }
        for (int e = threadIdx.x; e < BK * C4; e += 256) {
            int r = e >> 5, c4 = e & 31;
            int gk = k0 + r;
            float4 v = (gk < ke) ? reinterpret_cast<const float4*>(B)[gk * C4 + c4]
                                 : make_float4(0.f, 0.f, 0.f, 0.f);
            reinterpret_cast<float4*>(Bs)[e] = v;
        }
        __syncthreads();
        #pragma unroll
        for (int k = 0; k < BK; k++) {
            float a0 = As[r0 * BK + k];
            float a1 = As[r1 * BK + k];
            float4 b = reinterpret_cast<float4*>(Bs)[k * C4 + tx];
            acc00 += a0 * b.x; acc01 += a0 * b.y; acc02 += a0 * b.z; acc03 += a0 * b.w;
            acc10 += a1 * b.x; acc11 += a1 * b.y; acc12 += a1 * b.z; acc13 += a1 * b.w;
        }
        __syncthreads();
    }
    float* Cout = g_regp + (size_t)sk * RM * CH;
    int gr0 = bm + r0, gr1 = bm + r1;
    if (gr0 < RM)
        reinterpret_cast<float4*>(Cout)[gr0 * C4 + tx] = make_float4(acc00, acc01, acc02, acc03);
    if (gr1 < RM)
        reinterpret_cast<float4*>(Cout)[gr1 * C4 + tx] = make_float4(acc10, acc11, acc12, acc13);
}

// blend: E[region] = 0.8*E + 0.2*(sum of SK partials)
__global__ void k_blend(float* __restrict__ E) {
    int i = blockIdx.x * blockDim.x + threadIdx.x;
    if (i < RM * CH) {
        float s = g_regp[i] + g_regp[RM*CH + i] + g_regp[2*RM*CH + i] + g_regp[3*RM*CH + i];
        float* p = &E[(size_t)RR0 * CH + i];
        *p = 0.8f * (*p) + 0.2f * s;
    }
}

// ---------------- fused aggregate: entities then users, warp-per-row ----------------
#define EBLK (NE/8)   // 12500 entity blocks
#define UBLK (NU/8)   // 6250 user blocks

__global__ __launch_bounds__(256)
void k_agg(const float4* __restrict__ E, float4* __restrict__ Enext,
           float4* __restrict__ resE, float4* __restrict__ resU,
           const float4* __restrict__ W) {
    int lane = threadIdx.x & 31;
    int wline = threadIdx.x >> 5;

    if (blockIdx.x < EBLK) {
        __shared__ float4 sW[NREL * C4];
        for (int e = threadIdx.x; e < NREL * C4; e += 256) sW[e] = W[e];
        __syncthreads();

        int row = blockIdx.x * 8 + wline;
        int start = g_rowptr[row];
        int end   = g_rowptr[row + 1];

        float4 a0 = make_float4(0,0,0,0), a1 = make_float4(0,0,0,0);
        for (int base = start; base < end; base += 32) {
            int m = min(32, end - base);
            int p = (lane < m) ? g_pack[base + lane] : 0;
            int j = 0;
            for (; j + 4 <= m; j += 4) {
                int p0 = __shfl_sync(0xffffffffu, p, j);
                int p1 = __shfl_sync(0xffffffffu, p, j + 1);
                int p2 = __shfl_sync(0xffffffffu, p, j + 2);
                int p3 = __shfl_sync(0xffffffffu, p, j + 3);
                float4 e0 = E[(p0 & 0x1FFFF) * C4 + lane];
                float4 e1 = E[(p1 & 0x1FFFF) * C4 + lane];
                float4 e2 = E[(p2 & 0x1FFFF) * C4 + lane];
                float4 e3 = E[(p3 & 0x1FFFF) * C4 + lane];
                float4 w0 = sW[(p0 >> 17) * C4 + lane];
                float4 w1 = sW[(p1 >> 17) * C4 + lane];
                float4 w2 = sW[(p2 >> 17) * C4 + lane];
                float4 w3 = sW[(p3 >> 17) * C4 + lane];
                a0.x += e0.x*w0.x; a0.y += e0.y*w0.y; a0.z += e0.z*w0.z; a0.w += e0.w*w0.w;
                a1.x += e1.x*w1.x; a1.y += e1.y*w1.y; a1.z += e1.z*w1.z; a1.w += e1.w*w1.w;
                a0.x += e2.x*w2.x; a0.y += e2.y*w2.y; a0.z += e2.z*w2.z; a0.w += e2.w*w2.w;
                a1.x += e3.x*w3.x; a1.y += e3.y*w3.y; a1.z += e3.z*w3.z; a1.w += e3.w*w3.w;
            }
            for (; j < m; j++) {
                int pj = __shfl_sync(0xffffffffu, p, j);
                float4 ev = E[(pj & 0x1FFFF) * C4 + lane];
                float4 w  = sW[(pj >> 17) * C4 + lane];
                a0.x += ev.x*w.x; a0.y += ev.y*w.y; a0.z += ev.z*w.z; a0.w += ev.w*w.w;
            }
        }
        float4 acc = make_float4(a0.x+a1.x, a0.y+a1.y, a0.z+a1.z, a0.w+a1.w);
        int cnt = end - start;
        float inv = cnt ? (1.f / (float)cnt) : 0.f;
        acc.x *= inv; acc.y *= inv; acc.z *= inv; acc.w *= inv;

        float ss = acc.x*acc.x + acc.y*acc.y + acc.z*acc.z + acc.w*acc.w;
        #pragma unroll
        for (int o = 16; o; o >>= 1) ss += __shfl_xor_sync(0xffffffffu, ss, o);
        float scale = 1.f / fmaxf(sqrtf(ss), 1e-12f);
        float4 o4 = make_float4(acc.x*scale, acc.y*scale, acc.z*scale, acc.w*scale);

        Enext[row * C4 + lane] = o4;
        float4 rv = resE[row * C4 + lane];
        rv.x += o4.x; rv.y += o4.y; rv.z += o4.z; rv.w += o4.w;
        resE[row * C4 + lane] = rv;
    } else {
        int row = (blockIdx.x - EBLK) * 8 + wline;
        int start = g_rowptr[NE + row]     - NEDGE;
        int end   = g_rowptr[NE + row + 1] - NEDGE;

        float4 a0 = make_float4(0,0,0,0), a1 = make_float4(0,0,0,0);
        for (int base = start; base < end; base += 32) {
            int m = min(32, end - base);
            int   c = (lane < m) ? g_ucol[base + lane] : 0;
            float v = (lane < m) ? g_uval[base + lane] : 0.f;
            int j = 0;
            for (; j + 4 <= m; j += 4) {
                int   c0 = __shfl_sync(0xffffffffu, c, j);
                int   c1 = __shfl_sync(0xffffffffu, c, j + 1);
                int   c2 = __shfl_sync(0xffffffffu, c, j + 2);
                int   c3 = __shfl_sync(0xffffffffu, c, j + 3);
                float v0 = __shfl_sync(0xffffffffu, v, j);
                float v1 = __shfl_sync(0xffffffffu, v, j + 1);
                float v2 = __shfl_sync(0xffffffffu, v, j + 2);
                float v3 = __shfl_sync(0xffffffffu, v, j + 3);
                float4 e0 = E[c0 * C4 + lane];
                float4 e1 = E[c1 * C4 + lane];
                float4 e2 = E[c2 * C4 + lane];
                float4 e3 = E[c3 * C4 + lane];
                a0.x += v0*e0.x; a0.y += v0*e0.y; a0.z += v0*e0.z; a0.w += v0*e0.w;
                a1.x += v1*e1.x; a1.y += v1*e1.y; a1.z += v1*e1.z; a1.w += v1*e1.w;
                a0.x += v2*e2.x; a0.y += v2*e2.y; a0.z += v2*e2.z; a0.w += v2*e2.w;
                a1.x += v3*e3.x; a1.y += v3*e3.y; a1.z += v3*e3.z; a1.w += v3*e3.w;
            }
            for (; j < m; j++) {
                int   cj = __shfl_sync(0xffffffffu, c, j);
                float vj = __shfl_sync(0xffffffffu, v, j);
                float4 ev = E[cj * C4 + lane];
                a0.x += vj*ev.x; a0.y += vj*ev.y; a0.z += vj*ev.z; a0.w += vj*ev.w;
            }
        }
        float4 acc = make_float4(a0.x+a1.x, a0.y+a1.y, a0.z+a1.z, a0.w+a1.w);
        float ss = acc.x*acc.x + acc.y*acc.y + acc.z*acc.z + acc.w*acc.w;
        #pragma unroll
        for (int o = 16; o; o >>= 1) ss += __shfl_xor_sync(0xffffffffu, ss, o);
        float scale = 1.f / fmaxf(sqrtf(ss), 1e-12f);
        float4 o4 = make_float4(acc.x*scale, acc.y*scale, acc.z*scale, acc.w*scale);

        float4 rv = resU[row * C4 + lane];
        rv.x += o4.x; rv.y += o4.y; rv.z += o4.z; rv.w += o4.w;
        resU[row * C4 + lane] = rv;
    }
}

// ---------------- launch ----------------
extern "C" void kernel_launch(void* const* d_in, const int* in_sizes, int n_in,
                              void* d_out, int out_size) {
    const float* user_emb   = (const float*)d_in[0];
    const float* entity_emb = (const float*)d_in[1];
    const float* rwm        = (const float*)d_in[2];
    const float* weight     = (const float*)d_in[3];
    const float* ivals      = (const float*)d_in[4];
    const int*   ehead      = (const int*)d_in[5];
    const int*   etail      = (const int*)d_in[6];
    const int*   etype      = (const int*)d_in[7];
    const int*   irows      = (const int*)d_in[8];
    const int*   icols      = (const int*)d_in[9];
    float* out = (float*)d_out;

    float *pE0, *pE1;
    int *pCnt;
    unsigned long long *pLb;
    cudaGetSymbolAddress((void**)&pE0, g_E0);
    cudaGetSymbolAddress((void**)&pE1, g_E1);
    cudaGetSymbolAddress((void**)&pCnt, g_cnt);
    cudaGetSymbolAddress((void**)&pLb, g_lb);

    // residual init + working buffer init
    cudaMemcpyAsync(out, entity_emb, (size_t)NE * CH * sizeof(float), cudaMemcpyDeviceToDevice);
    cudaMemcpyAsync(out + (size_t)NE * CH, user_emb, (size_t)NU * CH * sizeof(float),
                    cudaMemcpyDeviceToDevice);
    cudaMemcpyAsync(pE0, entity_emb, (size_t)NE * CH * sizeof(float), cudaMemcpyDeviceToDevice);
    cudaMemsetAsync(pCnt, 0, NTOT * sizeof(int));
    cudaMemsetAsync(pLb, 0, NSCAN * sizeof(unsigned long long));

    float* Ecur = pE0;
    float* Enxt = pE1;

    dim3 ggemm(163, SK);

    // hop 1: gemm/blend first (independent of CSR), CSR build, then agg
    k_gemm_region<<<ggemm, 256>>>(rwm, Ecur + (size_t)RR0 * CH);
    k_blend<<<(RM * CH + 255) / 256, 256>>>(Ecur);
    k_count<<<(NEDGE + NNZV + 255) / 256, 256>>>(ehead, irows);
    k_scan_lb<<<NSCAN, 1024>>>();
    k_fill<<<(NEDGE + NNZV + 255) / 256, 256>>>(ehead, etail, etype, irows, icols, ivals);
    k_agg<<<EBLK + UBLK, 256>>>((const float4*)Ecur, (float4*)Enxt,
                                (float4*)out, (float4*)(out + (size_t)NE * CH),
                                (const float4*)weight);
    { float* t = Ecur; Ecur = Enxt; Enxt = t; }

    for (int h = 1; h < NHOPS; h++) {
        k_gemm_region<<<ggemm, 256>>>(rwm, Ecur + (size_t)RR0 * CH);
        k_blend<<<(RM * CH + 255) / 256, 256>>>(Ecur);
        k_agg<<<EBLK + UBLK, 256>>>((const float4*)Ecur, (float4*)Enxt,
                                    (float4*)out, (float4*)(out + (size_t)NE * CH),
                                    (const float4*)weight);
        float* t = Ecur; Ecur = Enxt; Enxt = t;
    }
}

// round 3
// speedup vs baseline: 1.8400x; 1.2783x over previous
#include <cuda_runtime.h>
#include <cuda_bf16.h>
#include <math.h>

// ---------------- problem constants ----------------
#define NE     100000
#define NU     50000
#define NTOT   (NE+NU)
#define NEDGE  2000000
#define NNZV   1000000
#define CH     128
#define C4     32
#define RR0    42033
#define RR1    44630
#define RM     (RR1-RR0)     // 2597
#define RMP    2624          // RM padded to 64
#define NREL   25
#define NHOPS  3
#define SK     4
#define KSL    672           // K-slice per split (mult of 32; 4*672 >= RM)
#define NSCAN  147

// ---------------- device scratch ----------------
__device__ float g_E0[NE*CH];
__device__ float g_E1[NE*CH];
__device__ float g_regp[SK*RM*CH];
__device__ __nv_bfloat16 g_Abf[RMP*RMP];   // zero-padded bf16 region matrix
__device__ __nv_bfloat16 g_Bbf[RMP*CH];    // rows >= RM stay 0 forever
__device__ int   g_cnt[NTOT];
__device__ int   g_rowptr[NTOT+1];
__device__ int   g_cursor[NTOT];
__device__ int   g_pack[NEDGE];
__device__ int   g_ucol[NNZV];
__device__ float g_uval[NNZV];
__device__ unsigned long long g_lb[NSCAN];

__device__ __forceinline__ unsigned pack_bf2(float x, float y) {
    __nv_bfloat162 t = __floats2bfloat162_rn(x, y);
    return *reinterpret_cast<unsigned*>(&t);
}

// ---------------- fused setup: count + cvtB + cvtA ----------------
#define NCVB (RM*C4)                 // 83104
#define NCVA (RMP*RMP/4)             // 1721344
#define NSETUP (NEDGE + NNZV + NCVB + NCVA)

__global__ void k_setup(const int* __restrict__ ehead, const int* __restrict__ irows,
                        const float* __restrict__ rwm, const float4* __restrict__ E0) {
    int i = blockIdx.x * blockDim.x + threadIdx.x;
    if (i < NEDGE) {
        atomicAdd(&g_cnt[ehead[i]], 1);
    } else if (i < NEDGE + NNZV) {
        atomicAdd(&g_cnt[NE + irows[i - NEDGE]], 1);
    } else if (i < NEDGE + NNZV + NCVB) {
        int j = i - (NEDGE + NNZV);
        int r = j >> 5, c = j & 31;
        float4 v = E0[(RR0 + r) * C4 + c];
        uint2 o; o.x = pack_bf2(v.x, v.y); o.y = pack_bf2(v.z, v.w);
        *reinterpret_cast<uint2*>(&g_Bbf[r * CH + c * 4]) = o;
    } else if (i < NSETUP) {
        int j = i - (NEDGE + NNZV + NCVB);
        int r = j / (RMP / 4), c = (j % (RMP / 4)) * 4;
        float v0 = 0, v1 = 0, v2 = 0, v3 = 0;
        if (r < RM) {
            const float* row = rwm + (size_t)r * RM;
            if (c + 0 < RM) v0 = row[c + 0];
            if (c + 1 < RM) v1 = row[c + 1];
            if (c + 2 < RM) v2 = row[c + 2];
            if (c + 3 < RM) v3 = row[c + 3];
        }
        uint2 o; o.x = pack_bf2(v0, v1); o.y = pack_bf2(v2, v3);
        *reinterpret_cast<uint2*>(&g_Abf[(size_t)r * RMP + c]) = o;
    }
}

// ---------------- decoupled-lookback exclusive scan (self-resets g_cnt) ----------------
__global__ __launch_bounds__(1024)
void k_scan_lb() {
    __shared__ int s[1024];
    __shared__ int s_prefix;
    int b = blockIdx.x, t = threadIdx.x;
    int i = b * 1024 + t;
    int v = (i < NTOT) ? g_cnt[i] : 0;
    if (i < NTOT) g_cnt[i] = 0;          // reset for next graph replay
    s[t] = v;
    __syncthreads();
    #pragma unroll
    for (int off = 1; off < 1024; off <<= 1) {
        int tmp = (t >= off) ? s[t - off] : 0;
        __syncthreads();
        s[t] += tmp;
        __syncthreads();
    }
    int incl = s[t];
    int total = s[1023];
    if (t == 0) {
        if (b == 0) {
            atomicExch(&g_lb[0], (2ULL << 32) | (unsigned)total);
            s_prefix = 0;
        } else {
            atomicExch(&g_lb[b], (1ULL << 32) | (unsigned)total);
            long long ex = 0;
            int idx = b - 1;
            while (true) {
                unsigned long long pk;
                do { pk = atomicAdd(&g_lb[idx], 0ULL); } while ((pk >> 32) == 0);
                ex += (unsigned)pk;
                if ((pk >> 32) == 2ULL) break;
                idx--;
            }
            atomicExch(&g_lb[b], (2ULL << 32) | (unsigned)(ex + total));
            s_prefix = (int)ex;
        }
    }
    __syncthreads();
    int excl = s_prefix + incl - v;
    if (i < NTOT) { g_rowptr[i] = excl; g_cursor[i] = excl; }
    if (i == NTOT - 1) g_rowptr[NTOT] = NEDGE + NNZV;
}

__global__ void k_fill(const int* __restrict__ ehead, const int* __restrict__ etail,
                       const int* __restrict__ etype, const int* __restrict__ irows,
                       const int* __restrict__ icols, const float* __restrict__ ivals) {
    int i = blockIdx.x * blockDim.x + threadIdx.x;
    if (i < NSCAN) g_lb[i] = 0;          // reset lookback state for next replay
    if (i < NEDGE) {
        int pos = atomicAdd(&g_cursor[ehead[i]], 1);
        g_pack[pos] = etail[i] | ((etype[i] - 1) << 17);
    } else if (i < NEDGE + NNZV) {
        int k = i - NEDGE;
        int pos = atomicAdd(&g_cursor[NE + irows[k]], 1) - NEDGE;
        g_ucol[pos] = icols[k];
        g_uval[pos] = ivals[k];
    }
}

// ---------------- bf16 tensor-core region GEMM, split-K ----------------
__device__ __forceinline__ void ldsm4(unsigned* r, const void* p) {
    unsigned a = (unsigned)__cvta_generic_to_shared(p);
    asm volatile("ldmatrix.sync.aligned.m8n8.x4.shared.b16 {%0,%1,%2,%3},[%4];"
        : "=r"(r[0]), "=r"(r[1]), "=r"(r[2]), "=r"(r[3]) : "r"(a));
}
__device__ __forceinline__ void ldsm4t(unsigned* r, const void* p) {
    unsigned a = (unsigned)__cvta_generic_to_shared(p);
    asm volatile("ldmatrix.sync.aligned.m8n8.x4.trans.shared.b16 {%0,%1,%2,%3},[%4];"
        : "=r"(r[0]), "=r"(r[1]), "=r"(r[2]), "=r"(r[3]) : "r"(a));
}
__device__ __forceinline__ void mma_bf16(float* d, const unsigned* a, const unsigned* b) {
    asm volatile("mma.sync.aligned.m16n8k16.row.col.f32.bf16.bf16.f32 "
        "{%0,%1,%2,%3},{%4,%5,%6,%7},{%8,%9},{%0,%1,%2,%3};"
        : "+f"(d[0]), "+f"(d[1]), "+f"(d[2]), "+f"(d[3])
        : "r"(a[0]), "r"(a[1]), "r"(a[2]), "r"(a[3]), "r"(b[0]), "r"(b[1]));
}

#define SA_STR 40    // bf16 stride, conflict-free for ldmatrix
#define SB_STR 136

__global__ __launch_bounds__(256)
void k_gemm_mma() {
    __shared__ __align__(16) __nv_bfloat16 sA[64 * SA_STR];
    __shared__ __align__(16) __nv_bfloat16 sB[32 * SB_STR];
    int bm = blockIdx.x * 64;
    int sk = blockIdx.y;
    int kb = sk * KSL;
    int ke = min(kb + KSL, RM);
    int tid = threadIdx.x, lane = tid & 31, w = tid >> 5;
    int wm = (w >> 1) * 16, wn = (w & 1) * 64;
    float acc[8][4];
    #pragma unroll
    for (int t = 0; t < 8; t++) { acc[t][0] = acc[t][1] = acc[t][2] = acc[t][3] = 0.f; }

    for (int k0 = kb; k0 < ke; k0 += 32) {
        #pragma unroll
        for (int e = tid; e < 512; e += 256) {       // A: 64x32
            int r = e >> 3, c = (e & 7) * 4;
            *reinterpret_cast<uint2*>(&sA[r * SA_STR + c]) =
                *reinterpret_cast<const uint2*>(&g_Abf[(size_t)(bm + r) * RMP + k0 + c]);
        }
        #pragma unroll
        for (int e = tid; e < 1024; e += 256) {      // B: 32x128
            int r = e >> 5, c = (e & 31) * 4;
            *reinterpret_cast<uint2*>(&sB[r * SB_STR + c]) =
                *reinterpret_cast<const uint2*>(&g_Bbf[(k0 + r) * CH + c]);
        }
        __syncthreads();
        #pragma unroll
        for (int kk = 0; kk < 32; kk += 16) {
            unsigned a[4];
            ldsm4(a, &sA[(wm + (lane & 15)) * SA_STR + kk + (lane >> 4) * 8]);
            #pragma unroll
            for (int nt = 0; nt < 4; nt++) {
                unsigned b[4];
                ldsm4t(b, &sB[(kk + (lane & 15)) * SB_STR + wn + nt * 16 + (lane >> 4) * 8]);
                mma_bf16(acc[nt * 2],     a, b);
                mma_bf16(acc[nt * 2 + 1], a, b + 2);
            }
        }
        __syncthreads();
    }
    float* C = g_regp + (size_t)sk * RM * CH;
    int g = lane >> 2, tig = lane & 3;
    #pragma unroll
    for (int t = 0; t < 8; t++) {
        int row = bm + wm + g, col = wn + t * 8 + tig * 2;
        if (row < RM)
            *reinterpret_cast<float2*>(&C[(size_t)row * CH + col]) = make_float2(acc[t][0], acc[t][1]);
        if (row + 8 < RM)
            *reinterpret_cast<float2*>(&C[(size_t)(row + 8) * CH + col]) = make_float2(acc[t][2], acc[t][3]);
    }
}

__global__ void k_blend(float* __restrict__ E) {
    int i = blockIdx.x * blockDim.x + threadIdx.x;
    if (i < RM * CH) {
        float s = g_regp[i] + g_regp[RM*CH + i] + g_regp[2*RM*CH + i] + g_regp[3*RM*CH + i];
        float* p = &E[(size_t)RR0 * CH + i];
        *p = 0.8f * (*p) + 0.2f * s;
    }
}

// ---------------- fused aggregate (entities + users), warp-per-row ----------------
#define EBLK (NE/8)
#define UBLK (NU/8)

__global__ __launch_bounds__(256)
void k_agg(const float4* __restrict__ E, float4* __restrict__ Enext,
           float4* __restrict__ resE, float4* __restrict__ resU,
           const float4* __restrict__ W) {
    int lane = threadIdx.x & 31;
    int wline = threadIdx.x >> 5;

    if (blockIdx.x < EBLK) {
        __shared__ float4 sW[NREL * C4];
        for (int e = threadIdx.x; e < NREL * C4; e += 256) sW[e] = W[e];
        __syncthreads();

        int row = blockIdx.x * 8 + wline;
        int start = g_rowptr[row];
        int end   = g_rowptr[row + 1];

        float4 a0 = make_float4(0,0,0,0), a1 = make_float4(0,0,0,0);
        for (int base = start; base < end; base += 32) {
            int m = min(32, end - base);
            int p = (lane < m) ? g_pack[base + lane] : 0;
            int j = 0;
            for (; j + 4 <= m; j += 4) {
                int p0 = __shfl_sync(0xffffffffu, p, j);
                int p1 = __shfl_sync(0xffffffffu, p, j + 1);
                int p2 = __shfl_sync(0xffffffffu, p, j + 2);
                int p3 = __shfl_sync(0xffffffffu, p, j + 3);
                float4 e0 = E[(p0 & 0x1FFFF) * C4 + lane];
                float4 e1 = E[(p1 & 0x1FFFF) * C4 + lane];
                float4 e2 = E[(p2 & 0x1FFFF) * C4 + lane];
                float4 e3 = E[(p3 & 0x1FFFF) * C4 + lane];
                float4 w0 = sW[(p0 >> 17) * C4 + lane];
                float4 w1 = sW[(p1 >> 17) * C4 + lane];
                float4 w2 = sW[(p2 >> 17) * C4 + lane];
                float4 w3 = sW[(p3 >> 17) * C4 + lane];
                a0.x += e0.x*w0.x; a0.y += e0.y*w0.y; a0.z += e0.z*w0.z; a0.w += e0.w*w0.w;
                a1.x += e1.x*w1.x; a1.y += e1.y*w1.y; a1.z += e1.z*w1.z; a1.w += e1.w*w1.w;
                a0.x += e2.x*w2.x; a0.y += e2.y*w2.y; a0.z += e2.z*w2.z; a0.w += e2.w*w2.w;
                a1.x += e3.x*w3.x; a1.y += e3.y*w3.y; a1.z += e3.z*w3.z; a1.w += e3.w*w3.w;
            }
            for (; j < m; j++) {
                int pj = __shfl_sync(0xffffffffu, p, j);
                float4 ev = E[(pj & 0x1FFFF) * C4 + lane];
                float4 w  = sW[(pj >> 17) * C4 + lane];
                a0.x += ev.x*w.x; a0.y += ev.y*w.y; a0.z += ev.z*w.z; a0.w += ev.w*w.w;
            }
        }
        float4 acc = make_float4(a0.x+a1.x, a0.y+a1.y, a0.z+a1.z, a0.w+a1.w);
        int cnt = end - start;
        float inv = cnt ? (1.f / (float)cnt) : 0.f;
        acc.x *= inv; acc.y *= inv; acc.z *= inv; acc.w *= inv;

        float ss = acc.x*acc.x + acc.y*acc.y + acc.z*acc.z + acc.w*acc.w;
        #pragma unroll
        for (int o = 16; o; o >>= 1) ss += __shfl_xor_sync(0xffffffffu, ss, o);
        float scale = 1.f / fmaxf(sqrtf(ss), 1e-12f);
        float4 o4 = make_float4(acc.x*scale, acc.y*scale, acc.z*scale, acc.w*scale);

        Enext[row * C4 + lane] = o4;
        // fused bf16 conversion of region rows for next hop's GEMM B operand
        if (row >= RR0 && row < RR1) {
            uint2 ob; ob.x = pack_bf2(o4.x, o4.y); ob.y = pack_bf2(o4.z, o4.w);
            *reinterpret_cast<uint2*>(&g_Bbf[(row - RR0) * CH + lane * 4]) = ob;
        }
        float4 rv = resE[row * C4 + lane];
        rv.x += o4.x; rv.y += o4.y; rv.z += o4.z; rv.w += o4.w;
        resE[row * C4 + lane] = rv;
    } else {
        int row = (blockIdx.x - EBLK) * 8 + wline;
        int start = g_rowptr[NE + row]     - NEDGE;
        int end   = g_rowptr[NE + row + 1] - NEDGE;

        float4 a0 = make_float4(0,0,0,0), a1 = make_float4(0,0,0,0);
        for (int base = start; base < end; base += 32) {
            int m = min(32, end - base);
            int   c = (lane < m) ? g_ucol[base + lane] : 0;
            float v = (lane < m) ? g_uval[base + lane] : 0.f;
            int j = 0;
            for (; j + 4 <= m; j += 4) {
                int   c0 = __shfl_sync(0xffffffffu, c, j);
                int   c1 = __shfl_sync(0xffffffffu, c, j + 1);
                int   c2 = __shfl_sync(0xffffffffu, c, j + 2);
                int   c3 = __shfl_sync(0xffffffffu, c, j + 3);
                float v0 = __shfl_sync(0xffffffffu, v, j);
                float v1 = __shfl_sync(0xffffffffu, v, j + 1);
                float v2 = __shfl_sync(0xffffffffu, v, j + 2);
                float v3 = __shfl_sync(0xffffffffu, v, j + 3);
                float4 e0 = E[c0 * C4 + lane];
                float4 e1 = E[c1 * C4 + lane];
                float4 e2 = E[c2 * C4 + lane];
                float4 e3 = E[c3 * C4 + lane];
                a0.x += v0*e0.x; a0.y += v0*e0.y; a0.z += v0*e0.z; a0.w += v0*e0.w;
                a1.x += v1*e1.x; a1.y += v1*e1.y; a1.z += v1*e1.z; a1.w += v1*e1.w;
                a0.x += v2*e2.x; a0.y += v2*e2.y; a0.z += v2*e2.z; a0.w += v2*e2.w;
                a1.x += v3*e3.x; a1.y += v3*e3.y; a1.z += v3*e3.z; a1.w += v3*e3.w;
            }
            for (; j < m; j++) {
                int   cj = __shfl_sync(0xffffffffu, c, j);
                float vj = __shfl_sync(0xffffffffu, v, j);
                float4 ev = E[cj * C4 + lane];
                a0.x += vj*ev.x; a0.y += vj*ev.y; a0.z += vj*ev.z; a0.w += vj*ev.w;
            }
        }
        float4 acc = make_float4(a0.x+a1.x, a0.y+a1.y, a0.z+a1.z, a0.w+a1.w);
        float ss = acc.x*acc.x + acc.y*acc.y + acc.z*acc.z + acc.w*acc.w;
        #pragma unroll
        for (int o = 16; o; o >>= 1) ss += __shfl_xor_sync(0xffffffffu, ss, o);
        float scale = 1.f / fmaxf(sqrtf(ss), 1e-12f);
        float4 o4 = make_float4(acc.x*scale, acc.y*scale, acc.z*scale, acc.w*scale);

        float4 rv = resU[row * C4 + lane];
        rv.x += o4.x; rv.y += o4.y; rv.z += o4.z; rv.w += o4.w;
        resU[row * C4 + lane] = rv;
    }
}

// ---------------- launch ----------------
extern "C" void kernel_launch(void* const* d_in, const int* in_sizes, int n_in,
                              void* d_out, int out_size) {
    const float* user_emb   = (const float*)d_in[0];
    const float* entity_emb = (const float*)d_in[1];
    const float* rwm        = (const float*)d_in[2];
    const float* weight     = (const float*)d_in[3];
    const float* ivals      = (const float*)d_in[4];
    const int*   ehead      = (const int*)d_in[5];
    const int*   etail      = (const int*)d_in[6];
    const int*   etype      = (const int*)d_in[7];
    const int*   irows      = (const int*)d_in[8];
    const int*   icols      = (const int*)d_in[9];
    float* out = (float*)d_out;

    float *pE0, *pE1;
    cudaGetSymbolAddress((void**)&pE0, g_E0);
    cudaGetSymbolAddress((void**)&pE1, g_E1);

    cudaMemcpyAsync(out, entity_emb, (size_t)NE * CH * sizeof(float), cudaMemcpyDeviceToDevice);
    cudaMemcpyAsync(out + (size_t)NE * CH, user_emb, (size_t)NU * CH * sizeof(float),
                    cudaMemcpyDeviceToDevice);
    cudaMemcpyAsync(pE0, entity_emb, (size_t)NE * CH * sizeof(float), cudaMemcpyDeviceToDevice);

    float* Ecur = pE0;
    float* Enxt = pE1;

    dim3 ggemm((RMP + 63) / 64, SK);   // (41, 4)

    // launches: setup(1) scan(2) fill(3) gemm(4) blend(5) agg(6) <- ncu -s 5 captures agg
    k_setup<<<(NSETUP + 255) / 256, 256>>>(ehead, irows, rwm, (const float4*)Ecur);
    k_scan_lb<<<NSCAN, 1024>>>();
    k_fill<<<(NEDGE + NNZV + 255) / 256, 256>>>(ehead, etail, etype, irows, icols, ivals);
    k_gemm_mma<<<ggemm, 256>>>();
    k_blend<<<(RM * CH + 255) / 256, 256>>>(Ecur);
    k_agg<<<EBLK + UBLK, 256>>>((const float4*)Ecur, (float4*)Enxt,
                                (float4*)out, (float4*)(out + (size_t)NE * CH),
                                (const float4*)weight);
    { float* t = Ecur; Ecur = Enxt; Enxt = t; }

    for (int h = 1; h < NHOPS; h++) {
        k_gemm_mma<<<ggemm, 256>>>();
        k_blend<<<(RM * CH + 255) / 256, 256>>>(Ecur);
        k_agg<<<EBLK + UBLK, 256>>>((const float4*)Ecur, (float4*)Enxt,
                                    (float4*)out, (float4*)(out + (size_t)NE * CH),
                                    (const float4*)weight);
        float* t = Ecur; Ecur = Enxt; Enxt = t;
    }
}

// round 5
// speedup vs baseline: 2.3050x; 1.2527x over previous
#include <cuda_runtime.h>
#include <cuda_fp16.h>
#include <math.h>

// ---------------- problem constants ----------------
#define NE     100000
#define NU     50000
#define NTOT   (NE+NU)
#define NEDGE  2000000
#define NNZV   1000000
#define CH     128
#define C4     32
#define CHH2   64            // CH/2 half2 per row
#define RR0    42033
#define RR1    44630
#define RM     (RR1-RR0)     // 2597
#define RMP    2624          // RM padded to 64
#define NREL   25
#define NHOPS  3
#define SK     8
#define NSCAN  147

// ---------------- device scratch ----------------
__device__ __half g_Eh0[NE*CH];            // fp16 entity tables (ping/pong)
__device__ __half g_Eh1[NE*CH];
__device__ __half g_Ah[RMP*RMP];           // zero-padded fp16 region matrix
__device__ float g_regp[SK*RM*CH];         // split-K partials
__device__ int   g_cnt[NTOT];
__device__ int   g_rowptr[NTOT+1];
__device__ int   g_cursor[NTOT];
__device__ int   g_pack[NEDGE];            // tail | ((type-1)<<17)
__device__ int   g_ucol[NNZV];
__device__ float g_uval[NNZV];
__device__ unsigned long long g_lb[NSCAN];

// ---------------- helpers ----------------
__device__ __forceinline__ uint2 f4toh4(float4 v) {
    __half2 a = __floats2half2_rn(v.x, v.y);
    __half2 b = __floats2half2_rn(v.z, v.w);
    uint2 o; o.x = *reinterpret_cast<unsigned*>(&a); o.y = *reinterpret_cast<unsigned*>(&b);
    return o;
}
__device__ __forceinline__ float4 h4tof4(uint2 u) {
    __half2 a = *reinterpret_cast<__half2*>(&u.x);
    __half2 b = *reinterpret_cast<__half2*>(&u.y);
    float2 fa = __half22float2(a), fb = __half22float2(b);
    return make_float4(fa.x, fa.y, fb.x, fb.y);
}
__device__ __forceinline__ void cpa16(void* dst, const void* src) {
    unsigned d = (unsigned)__cvta_generic_to_shared(dst);
    asm volatile("cp.async.cg.shared.global [%0],[%1],16;\n" :: "r"(d), "l"(src));
}
#define CP_COMMIT() asm volatile("cp.async.commit_group;\n")
#define CP_WAIT1()  asm volatile("cp.async.wait_group 1;\n")

// ---------------- fused setup: count + cvtA + cvtE ----------------
#define NCVE (NE*C4)                 // 3,200,000 float4 -> uint2
#define NCVA (RMP*RMP/4)             // 1,721,344
#define NSETUP (NEDGE + NNZV + NCVE + NCVA)

__global__ void k_setup(const int* __restrict__ ehead, const int* __restrict__ irows,
                        const float* __restrict__ rwm, const float4* __restrict__ E0) {
    int i = blockIdx.x * blockDim.x + threadIdx.x;
    if (i < NEDGE) {
        atomicAdd(&g_cnt[ehead[i]], 1);
    } else if (i < NEDGE + NNZV) {
        atomicAdd(&g_cnt[NE + irows[i - NEDGE]], 1);
    } else if (i < NEDGE + NNZV + NCVE) {
        int j = i - (NEDGE + NNZV);
        reinterpret_cast<uint2*>(g_Eh0)[j] = f4toh4(E0[j]);
    } else if (i < NSETUP) {
        int j = i - (NEDGE + NNZV + NCVE);
        int r = j / (RMP / 4), c = (j % (RMP / 4)) * 4;
        float v0 = 0, v1 = 0, v2 = 0, v3 = 0;
        if (r < RM) {
            const float* row = rwm + (size_t)r * RM;
            if (c + 0 < RM) v0 = row[c + 0];
            if (c + 1 < RM) v1 = row[c + 1];
            if (c + 2 < RM) v2 = row[c + 2];
            if (c + 3 < RM) v3 = row[c + 3];
        }
        *reinterpret_cast<uint2*>(&g_Ah[(size_t)r * RMP + c]) =
            f4toh4(make_float4(v0, v1, v2, v3));
    }
}

// ---------------- decoupled-lookback exclusive scan (self-resets g_cnt) ----------------
__global__ __launch_bounds__(1024)
void k_scan_lb() {
    __shared__ int s[1024];
    __shared__ int s_prefix;
    int b = blockIdx.x, t = threadIdx.x;
    int i = b * 1024 + t;
    int v = (i < NTOT) ? g_cnt[i] : 0;
    if (i < NTOT) g_cnt[i] = 0;
    s[t] = v;
    __syncthreads();
    #pragma unroll
    for (int off = 1; off < 1024; off <<= 1) {
        int tmp = (t >= off) ? s[t - off] : 0;
        __syncthreads();
        s[t] += tmp;
        __syncthreads();
    }
    int incl = s[t];
    int total = s[1023];
    if (t == 0) {
        if (b == 0) {
            atomicExch(&g_lb[0], (2ULL << 32) | (unsigned)total);
            s_prefix = 0;
        } else {
            atomicExch(&g_lb[b], (1ULL << 32) | (unsigned)total);
            long long ex = 0;
            int idx = b - 1;
            while (true) {
                unsigned long long pk;
                do { pk = atomicAdd(&g_lb[idx], 0ULL); } while ((pk >> 32) == 0);
                ex += (unsigned)pk;
                if ((pk >> 32) == 2ULL) break;
                idx--;
            }
            atomicExch(&g_lb[b], (2ULL << 32) | (unsigned)(ex + total));
            s_prefix = (int)ex;
        }
    }
    __syncthreads();
    int excl = s_prefix + incl - v;
    if (i < NTOT) { g_rowptr[i] = excl; g_cursor[i] = excl; }
    if (i == NTOT - 1) g_rowptr[NTOT] = NEDGE + NNZV;
}

__global__ void k_fill(const int* __restrict__ ehead, const int* __restrict__ etail,
                       const int* __restrict__ etype, const int* __restrict__ irows,
                       const int* __restrict__ icols, const float* __restrict__ ivals) {
    int i = blockIdx.x * blockDim.x + threadIdx.x;
    if (i < NSCAN) g_lb[i] = 0;
    if (i < NEDGE) {
        int pos = atomicAdd(&g_cursor[ehead[i]], 1);
        g_pack[pos] = etail[i] | ((etype[i] - 1) << 17);
    } else if (i < NEDGE + NNZV) {
        int k = i - NEDGE;
        int pos = atomicAdd(&g_cursor[NE + irows[k]], 1) - NEDGE;
        g_ucol[pos] = icols[k];
        g_uval[pos] = ivals[k];
    }
}

// ---------------- fp16 tensor-core region GEMM, split-K 8, cp.async 2-stage ----------------
__device__ __forceinline__ void ldsm4(unsigned* r, const void* p) {
    unsigned a = (unsigned)__cvta_generic_to_shared(p);
    asm volatile("ldmatrix.sync.aligned.m8n8.x4.shared.b16 {%0,%1,%2,%3},[%4];"
        : "=r"(r[0]), "=r"(r[1]), "=r"(r[2]), "=r"(r[3]) : "r"(a));
}
__device__ __forceinline__ void ldsm4t(unsigned* r, const void* p) {
    unsigned a = (unsigned)__cvta_generic_to_shared(p);
    asm volatile("ldmatrix.sync.aligned.m8n8.x4.trans.shared.b16 {%0,%1,%2,%3},[%4];"
        : "=r"(r[0]), "=r"(r[1]), "=r"(r[2]), "=r"(r[3]) : "r"(a));
}
__device__ __forceinline__ void mma_f16(float* d, const unsigned* a, const unsigned* b) {
    asm volatile("mma.sync.aligned.m16n8k16.row.col.f32.f16.f16.f32 "
        "{%0,%1,%2,%3},{%4,%5,%6,%7},{%8,%9},{%0,%1,%2,%3};"
        : "+f"(d[0]), "+f"(d[1]), "+f"(d[2]), "+f"(d[3])
        : "r"(a[0]), "r"(a[1]), "r"(a[2]), "r"(a[3]), "r"(b[0]), "r"(b[1]));
}

#define SA_STR 40
#define SB_STR 136

__global__ __launch_bounds__(256)
void k_gemm_mma(const __half* __restrict__ Bsrc /* Ecur + RR0*CH */) {
    __shared__ __align__(16) __half sA[2][64 * SA_STR];
    __shared__ __align__(16) __half sB[2][32 * SB_STR];
    int bm = blockIdx.x * 64;
    int sk = blockIdx.y;
    int kb = sk * 320;
    int ke = (sk == SK - 1) ? RMP : kb + 320;
    int iters = (ke - kb) >> 5;
    int tid = threadIdx.x, lane = tid & 31, w = tid >> 5;
    int wm = (w >> 1) * 16, wn = (w & 1) * 64;

    float acc[8][4];
    #pragma unroll
    for (int t = 0; t < 8; t++) { acc[t][0] = acc[t][1] = acc[t][2] = acc[t][3] = 0.f; }

    // stage loader (A: 64x32 = 256 x 16B chunks, B: 32x128 = 512 x 16B chunks)
    auto load_stage = [&](int s, int k0) {
        {
            int r = tid >> 2, c = (tid & 3) * 8;   // FIXED: 64 rows x 4 chunks
            cpa16(&sA[s][r * SA_STR + c], &g_Ah[(size_t)(bm + r) * RMP + k0 + c]);
        }
        #pragma unroll
        for (int i2 = 0; i2 < 2; i2++) {
            int e = tid + i2 * 256;
            int r = e >> 4, c = (e & 15) * 8;
            cpa16(&sB[s][r * SB_STR + c], &Bsrc[(size_t)(k0 + r) * CH + c]);
        }
    };

    load_stage(0, kb);
    CP_COMMIT();

    for (int it = 0; it < iters; it++) {
        if (it + 1 < iters) load_stage((it + 1) & 1, kb + (it + 1) * 32);
        CP_COMMIT();
        CP_WAIT1();
        __syncthreads();
        int s = it & 1;
        #pragma unroll
        for (int kk = 0; kk < 32; kk += 16) {
            unsigned a[4];
            ldsm4(a, &sA[s][(wm + (lane & 15)) * SA_STR + kk + (lane >> 4) * 8]);
            #pragma unroll
            for (int nt = 0; nt < 4; nt++) {
                unsigned b[4];
                ldsm4t(b, &sB[s][(kk + (lane & 15)) * SB_STR + wn + nt * 16 + (lane >> 4) * 8]);
                mma_f16(acc[nt * 2],     a, b);
                mma_f16(acc[nt * 2 + 1], a, b + 2);
            }
        }
        __syncthreads();
    }

    float* C = g_regp + (size_t)sk * RM * CH;
    int g = lane >> 2, tig = lane & 3;
    #pragma unroll
    for (int t = 0; t < 8; t++) {
        int row = bm + wm + g, col = wn + t * 8 + tig * 2;
        if (row < RM)
            *reinterpret_cast<float2*>(&C[(size_t)row * CH + col]) = make_float2(acc[t][0], acc[t][1]);
        if (row + 8 < RM)
            *reinterpret_cast<float2*>(&C[(size_t)(row + 8) * CH + col]) = make_float2(acc[t][2], acc[t][3]);
    }
}

// blend: E[region] = 0.8*E + 0.2*(sum of SK partials), in-place on half storage
__global__ void k_blend(__half2* __restrict__ Eh) {
    int i = blockIdx.x * blockDim.x + threadIdx.x;
    if (i < RM * CH / 2) {
        float sx = 0.f, sy = 0.f;
        #pragma unroll
        for (int s = 0; s < SK; s++) {
            float2 p = *reinterpret_cast<const float2*>(&g_regp[(size_t)s * RM * CH + 2 * i]);
            sx += p.x; sy += p.y;
        }
        float2 ef = __half22float2(Eh[(size_t)RR0 * CHH2 + i]);
        Eh[(size_t)RR0 * CHH2 + i] = __floats2half2_rn(0.8f * ef.x + 0.2f * sx,
                                                       0.8f * ef.y + 0.2f * sy);
    }
}

// ---------------- fused aggregate (entities + users), warp-per-row ----------------
#define EBLK (NE/8)
#define UBLK (NU/8)

__global__ __launch_bounds__(256)
void k_agg(const uint2* __restrict__ E, uint2* __restrict__ Enext,
           float4* __restrict__ resE, float4* __restrict__ resU,
           const float4* __restrict__ W) {
    int lane = threadIdx.x & 31;
    int wline = threadIdx.x >> 5;

    if (blockIdx.x < EBLK) {
        __shared__ float4 sW[NREL * C4];
        for (int e = threadIdx.x; e < NREL * C4; e += 256) sW[e] = W[e];
        __syncthreads();

        int row = blockIdx.x * 8 + wline;
        int start = g_rowptr[row];
        int end   = g_rowptr[row + 1];

        float4 a0 = make_float4(0,0,0,0), a1 = make_float4(0,0,0,0);
        for (int base = start; base < end; base += 32) {
            int m = min(32, end - base);
            int p = (lane < m) ? g_pack[base + lane] : 0;
            int j = 0;
            for (; j + 4 <= m; j += 4) {
                int p0 = __shfl_sync(0xffffffffu, p, j);
                int p1 = __shfl_sync(0xffffffffu, p, j + 1);
                int p2 = __shfl_sync(0xffffffffu, p, j + 2);
                int p3 = __shfl_sync(0xffffffffu, p, j + 3);
                float4 e0 = h4tof4(E[(p0 & 0x1FFFF) * C4 + lane]);
                float4 e1 = h4tof4(E[(p1 & 0x1FFFF) * C4 + lane]);
                float4 e2 = h4tof4(E[(p2 & 0x1FFFF) * C4 + lane]);
                float4 e3 = h4tof4(E[(p3 & 0x1FFFF) * C4 + lane]);
                float4 w0 = sW[(p0 >> 17) * C4 + lane];
                float4 w1 = sW[(p1 >> 17) * C4 + lane];
                float4 w2 = sW[(p2 >> 17) * C4 + lane];
                float4 w3 = sW[(p3 >> 17) * C4 + lane];
                a0.x += e0.x*w0.x; a0.y += e0.y*w0.y; a0.z += e0.z*w0.z; a0.w += e0.w*w0.w;
                a1.x += e1.x*w1.x; a1.y += e1.y*w1.y; a1.z += e1.z*w1.z; a1.w += e1.w*w1.w;
                a0.x += e2.x*w2.x; a0.y += e2.y*w2.y; a0.z += e2.z*w2.z; a0.w += e2.w*w2.w;
                a1.x += e3.x*w3.x; a1.y += e3.y*w3.y; a1.z += e3.z*w3.z; a1.w += e3.w*w3.w;
            }
            for (; j < m; j++) {
                int pj = __shfl_sync(0xffffffffu, p, j);
                float4 ev = h4tof4(E[(pj & 0x1FFFF) * C4 + lane]);
                float4 w  = sW[(pj >> 17) * C4 + lane];
                a0.x += ev.x*w.x; a0.y += ev.y*w.y; a0.z += ev.z*w.z; a0.w += ev.w*w.w;
            }
        }
        float4 acc = make_float4(a0.x+a1.x, a0.y+a1.y, a0.z+a1.z, a0.w+a1.w);
        int cnt = end - start;
        float inv = cnt ? (1.f / (float)cnt) : 0.f;
        acc.x *= inv; acc.y *= inv; acc.z *= inv; acc.w *= inv;

        float ss = acc.x*acc.x + acc.y*acc.y + acc.z*acc.z + acc.w*acc.w;
        #pragma unroll
        for (int o = 16; o; o >>= 1) ss += __shfl_xor_sync(0xffffffffu, ss, o);
        float scale = 1.f / fmaxf(sqrtf(ss), 1e-12f);
        float4 o4 = make_float4(acc.x*scale, acc.y*scale, acc.z*scale, acc.w*scale);

        Enext[row * C4 + lane] = f4toh4(o4);
        float4 rv = resE[row * C4 + lane];
        rv.x += o4.x; rv.y += o4.y; rv.z += o4.z; rv.w += o4.w;
        resE[row * C4 + lane] = rv;
    } else {
        int row = (blockIdx.x - EBLK) * 8 + wline;
        int start = g_rowptr[NE + row]     - NEDGE;
        int end   = g_rowptr[NE + row + 1] - NEDGE;

        float4 a0 = make_float4(0,0,0,0), a1 = make_float4(0,0,0,0);
        for (int base = start; base < end; base += 32) {
            int m = min(32, end - base);
            int   c = (lane < m) ? g_ucol[base + lane] : 0;
            float v = (lane < m) ? g_uval[base + lane] : 0.f;
            int j = 0;
            for (; j + 4 <= m; j += 4) {
                int   c0 = __shfl_sync(0xffffffffu, c, j);
                int   c1 = __shfl_sync(0xffffffffu, c, j + 1);
                int   c2 = __shfl_sync(0xffffffffu, c, j + 2);
                int   c3 = __shfl_sync(0xffffffffu, c, j + 3);
                float v0 = __shfl_sync(0xffffffffu, v, j);
                float v1 = __shfl_sync(0xffffffffu, v, j + 1);
                float v2 = __shfl_sync(0xffffffffu, v, j + 2);
                float v3 = __shfl_sync(0xffffffffu, v, j + 3);
                float4 e0 = h4tof4(E[c0 * C4 + lane]);
                float4 e1 = h4tof4(E[c1 * C4 + lane]);
                float4 e2 = h4tof4(E[c2 * C4 + lane]);
                float4 e3 = h4tof4(E[c3 * C4 + lane]);
                a0.x += v0*e0.x; a0.y += v0*e0.y; a0.z += v0*e0.z; a0.w += v0*e0.w;
                a1.x += v1*e1.x; a1.y += v1*e1.y; a1.z += v1*e1.z; a1.w += v1*e1.w;
                a0.x += v2*e2.x; a0.y += v2*e2.y; a0.z += v2*e2.z; a0.w += v2*e2.w;
                a1.x += v3*e3.x; a1.y += v3*e3.y; a1.z += v3*e3.z; a1.w += v3*e3.w;
            }
            for (; j < m; j++) {
                int   cj = __shfl_sync(0xffffffffu, c, j);
                float vj = __shfl_sync(0xffffffffu, v, j);
                float4 ev = h4tof4(E[cj * C4 + lane]);
                a0.x += vj*ev.x; a0.y += vj*ev.y; a0.z += vj*ev.z; a0.w += vj*ev.w;
            }
        }
        float4 acc = make_float4(a0.x+a1.x, a0.y+a1.y, a0.z+a1.z, a0.w+a1.w);
        float ss = acc.x*acc.x + acc.y*acc.y + acc.z*acc.z + acc.w*acc.w;
        #pragma unroll
        for (int o = 16; o; o >>= 1) ss += __shfl_xor_sync(0xffffffffu, ss, o);
        float scale = 1.f / fmaxf(sqrtf(ss), 1e-12f);
        float4 o4 = make_float4(acc.x*scale, acc.y*scale, acc.z*scale, acc.w*scale);

        float4 rv = resU[row * C4 + lane];
        rv.x += o4.x; rv.y += o4.y; rv.z += o4.z; rv.w += o4.w;
        resU[row * C4 + lane] = rv;
    }
}

// ---------------- launch ----------------
extern "C" void kernel_launch(void* const* d_in, const int* in_sizes, int n_in,
                              void* d_out, int out_size) {
    const float* user_emb   = (const float*)d_in[0];
    const float* entity_emb = (const float*)d_in[1];
    const float* rwm        = (const float*)d_in[2];
    const float* weight     = (const float*)d_in[3];
    const float* ivals      = (const float*)d_in[4];
    const int*   ehead      = (const int*)d_in[5];
    const int*   etail      = (const int*)d_in[6];
    const int*   etype      = (const int*)d_in[7];
    const int*   irows      = (const int*)d_in[8];
    const int*   icols      = (const int*)d_in[9];
    float* out = (float*)d_out;

    __half *pEh0, *pEh1;
    cudaGetSymbolAddress((void**)&pEh0, g_Eh0);
    cudaGetSymbolAddress((void**)&pEh1, g_Eh1);

    cudaMemcpyAsync(out, entity_emb, (size_t)NE * CH * sizeof(float), cudaMemcpyDeviceToDevice);
    cudaMemcpyAsync(out + (size_t)NE * CH, user_emb, (size_t)NU * CH * sizeof(float),
                    cudaMemcpyDeviceToDevice);

    __half* Ecur = pEh0;
    __half* Enxt = pEh1;

    dim3 ggemm((RMP + 63) / 64, SK);   // (41, 8)

    k_setup<<<(NSETUP + 255) / 256, 256>>>(ehead, irows, rwm, (const float4*)entity_emb);
    k_scan_lb<<<NSCAN, 1024>>>();
    k_fill<<<(NEDGE + NNZV + 255) / 256, 256>>>(ehead, etail, etype, irows, icols, ivals);

    for (int h = 0; h < NHOPS; h++) {
        k_gemm_mma<<<ggemm, 256>>>(Ecur + (size_t)RR0 * CH);
        k_blend<<<(RM * CH / 2 + 255) / 256, 256>>>((__half2*)Ecur);
        k_agg<<<EBLK + UBLK, 256>>>((const uint2*)Ecur, (uint2*)Enxt,
                                    (float4*)out, (float4*)(out + (size_t)NE * CH),
                                    (const float4*)weight);
        __half* t = Ecur; Ecur = Enxt; Enxt = t;
    }
}